// round 10
// baseline (speedup 1.0000x reference)
#include <cuda_runtime.h>
#include <cuda_bf16.h>
#include <math.h>
#include <stdint.h>

#define SEQ    512
#define BATCH  64
#define D_IN   1024
#define D_H    1024
#define M_IN   (SEQ * BATCH)      // 32768
#define BH     (BATCH * D_H)      // 65536
#define GRID_P 128                // persistent blocks for recurrence

typedef unsigned long long ull;

// packed f32x2 helpers (FFMA2: only reachable via PTX fma.rn.f32x2)
__device__ __forceinline__ ull pk2(float lo, float hi) {
    ull r;
    asm("mov.b64 %0, {%1, %2};" : "=l"(r) : "r"(__float_as_uint(lo)), "r"(__float_as_uint(hi)));
    return r;
}
__device__ __forceinline__ void upk2(float& lo, float& hi, ull v) {
    uint32_t a, b;
    asm("mov.b64 {%0, %1}, %2;" : "=r"(a), "=r"(b) : "l"(v));
    lo = __uint_as_float(a); hi = __uint_as_float(b);
}
__device__ __forceinline__ ull fma2(ull a, ull b, ull c) {
    ull d;
    asm("fma.rn.f32x2 %0, %1, %2, %3;" : "=l"(d) : "l"(a), "l"(b), "l"(c));
    return d;
}

// ===========================================================================
// Persistent device state: barrier counter. Reset to 0 by the GEMM kernel
// (stream-ordered before the rnn kernel), so every run uses absolute targets.
// ===========================================================================
__device__ unsigned g_count;

// ===========================================================================
// Input projection: out[m][n] = sum_i x[m][i]*Wih[n][i] + bih[n] + bhh[n]
// M=32768, N=1024, K=1024. BM=BN=128, BK=16, 8x8 thread tile, 256 threads.
// (R8-proven body.) Block (0,0) resets the rnn barrier counter.
// ===========================================================================
__global__ __launch_bounds__(256) void input_gemm_kernel(
    const float* __restrict__ x, const float* __restrict__ Wih,
    const float* __restrict__ bih, const float* __restrict__ bhh,
    float* __restrict__ out)
{
    __shared__ __align__(16) float As[16][132];
    __shared__ __align__(16) float Bs[16][132];

    const int tid = threadIdx.x;
    if (blockIdx.x == 0 && blockIdx.y == 0 && tid == 0) g_count = 0u;

    const int m0 = blockIdx.y * 128;
    const int n0 = blockIdx.x * 128;
    const int tx = tid & 15;   // -> n
    const int ty = tid >> 4;   // -> m

    ull acc2[8][4];
    #pragma unroll
    for (int i = 0; i < 8; i++)
        #pragma unroll
        for (int j = 0; j < 4; j++) acc2[i][j] = 0ull;

    for (int k0 = 0; k0 < D_IN; k0 += 16) {
        #pragma unroll
        for (int l = 0; l < 2; l++) {
            int f = tid + l * 256;
            int r = f >> 2, c = (f & 3) * 4;
            float4 v = *(const float4*)(x + (size_t)(m0 + r) * D_IN + k0 + c);
            As[c + 0][r] = v.x; As[c + 1][r] = v.y;
            As[c + 2][r] = v.z; As[c + 3][r] = v.w;
        }
        #pragma unroll
        for (int l = 0; l < 2; l++) {
            int f = tid + l * 256;
            int r = f >> 2, c = (f & 3) * 4;
            float4 v = *(const float4*)(Wih + (size_t)(n0 + r) * D_IN + k0 + c);
            Bs[c + 0][r] = v.x; Bs[c + 1][r] = v.y;
            Bs[c + 2][r] = v.z; Bs[c + 3][r] = v.w;
        }
        __syncthreads();
        #pragma unroll
        for (int k = 0; k < 16; k++) {
            float a[8], b[8];
            *(float4*)&a[0] = *(const float4*)&As[k][ty * 8];
            *(float4*)&a[4] = *(const float4*)&As[k][ty * 8 + 4];
            *(float4*)&b[0] = *(const float4*)&Bs[k][tx * 8];
            *(float4*)&b[4] = *(const float4*)&Bs[k][tx * 8 + 4];
            ull b2[4];
            #pragma unroll
            for (int q = 0; q < 4; q++) b2[q] = pk2(b[2 * q], b[2 * q + 1]);
            #pragma unroll
            for (int i = 0; i < 8; i++) {
                ull a2 = pk2(a[i], a[i]);
                #pragma unroll
                for (int q = 0; q < 4; q++)
                    acc2[i][q] = fma2(a2, b2[q], acc2[i][q]);
            }
        }
        __syncthreads();
    }

    #pragma unroll
    for (int i = 0; i < 8; i++) {
        int m = m0 + ty * 8 + i;
        float accf[8];
        #pragma unroll
        for (int q = 0; q < 4; q++) upk2(accf[2 * q], accf[2 * q + 1], acc2[i][q]);
        #pragma unroll
        for (int j = 0; j < 8; j += 4) {
            int n = n0 + tx * 8 + j;
            float4 o;
            o.x = accf[j + 0] + bih[n + 0] + bhh[n + 0];
            o.y = accf[j + 1] + bih[n + 1] + bhh[n + 1];
            o.z = accf[j + 2] + bih[n + 2] + bhh[n + 2];
            o.w = accf[j + 3] + bih[n + 3] + bhh[n + 3];
            *(float4*)(out + (size_t)m * D_H + n) = o;
        }
    }
}

// ===========================================================================
// Persistent recurrence, batch-register-tiled.
// 128 blocks x 512 threads. Block bx owns cols j0 = bx*8.
// Thread (bg = tid>>5, lane = tid&31): 4 batches (bg*4..+3) x 8 cols x
// 32-k chunk (lane*32..). Each 32B W fragment from smem feeds 16 fma2
// (4x reuse vs R8 -> smem traffic 2MB -> 512KB per block-step).
// W layout: Ws2[lane*130 + i*4 + jp], 16B-aligned pitch, phase-conflict-free.
// Reduction: 31-shfl halving butterfly over the warp (lane l -> output l).
// h state lives in out: step t reads out[t-1] (t=0: h0).
// ===========================================================================
__global__ __launch_bounds__(512, 1) void rnn_persistent_kernel(
    const float* __restrict__ h0, const float* __restrict__ Whh,
    float* __restrict__ out, int write_tail)
{
    __shared__ __align__(16) ull Ws2[32 * 130];   // 33280 B

    const int tid = threadIdx.x;
    const int bx  = blockIdx.x;
    const int j0  = bx * 8;

    // One-time Whh slice load: dest[kc*130 + i*4 + jp] = (W[j0+2jp][k], W[j0+2jp+1][k])
    {
        const int k = tid * 2;                   // k, k+1 stay in one kc chunk
        const int base0 = (k >> 5) * 130 + (k & 31) * 4;
        #pragma unroll
        for (int jp = 0; jp < 4; jp++) {
            float2 wa = *(const float2*)(Whh + (size_t)(j0 + 2 * jp) * D_H + k);
            float2 wb = *(const float2*)(Whh + (size_t)(j0 + 2 * jp + 1) * D_H + k);
            Ws2[base0 + jp]     = pk2(wa.x, wb.x);
            Ws2[base0 + 4 + jp] = pk2(wa.y, wb.y);
        }
    }
    __syncthreads();

    const int bg   = tid >> 5;        // 0..15 batch group
    const int lane = tid & 31;        // = kc chunk id
    const int b0   = bg * 4;
    const int kb   = lane * 32;
    const ull* wrow = Ws2 + lane * 130;

    // after reduction, lane l owns output (b0 + (l>>3), j0 + (l&7))
    const int oidx = (b0 + (lane >> 3)) * D_H + j0 + (lane & 7);

    for (int t = 0; t < SEQ; t++) {
        const float* hsrc = (t == 0) ? h0 : out + (size_t)(t - 1) * BH;
        float* op = out + (size_t)t * BH + oidx;

        // prefetch xproj early (off the critical path)
        float xp = __ldcg(op);

        ull acc[4][4];                // [bb][jp]
        #pragma unroll
        for (int bb = 0; bb < 4; bb++)
            #pragma unroll
            for (int jp = 0; jp < 4; jp++) acc[bb][jp] = 0ull;

        #pragma unroll
        for (int i4 = 0; i4 < 32; i4 += 4) {
            float4 hv[4];
            #pragma unroll
            for (int bb = 0; bb < 4; bb++)
                hv[bb] = __ldcg((const float4*)(hsrc + (size_t)(b0 + bb) * D_H + kb + i4));
            #pragma unroll
            for (int u = 0; u < 4; u++) {
                ulonglong2 wA = *(const ulonglong2*)(wrow + (i4 + u) * 4);
                ulonglong2 wB = *(const ulonglong2*)(wrow + (i4 + u) * 4 + 2);
                #pragma unroll
                for (int bb = 0; bb < 4; bb++) {
                    float hk = ((const float*)&hv[bb])[u];
                    ull h2 = pk2(hk, hk);
                    acc[bb][0] = fma2(h2, wA.x, acc[bb][0]);
                    acc[bb][1] = fma2(h2, wA.y, acc[bb][1]);
                    acc[bb][2] = fma2(h2, wB.x, acc[bb][2]);
                    acc[bb][3] = fma2(h2, wB.y, acc[bb][3]);
                }
            }
        }

        // unpack to v[a], a = bb*8 + col (col = 2*jp + p)
        float v[32];
        #pragma unroll
        for (int bb = 0; bb < 4; bb++)
            #pragma unroll
            for (int jp = 0; jp < 4; jp++)
                upk2(v[bb * 8 + 2 * jp], v[bb * 8 + 2 * jp + 1], acc[bb][jp]);

        // halving butterfly: 31 shfl total; lane l ends with sum of v[l]
        #pragma unroll
        for (int s = 0; s < 5; s++) {
            const int m = 16 >> s;         // 16,8,4,2,1
            const bool hi = (lane & m) != 0;
            #pragma unroll
            for (int q = 0; q < 16; q++) { // only q < m is live
                if (q < m) {
                    float tsend = hi ? v[q] : v[q + m];
                    float r = __shfl_xor_sync(0xffffffffu, tsend, m);
                    v[q] = (hi ? v[q + m] : v[q]) + r;
                }
            }
        }

        float hv = tanhf(xp + v[0]);
        __stcg(op, hv);
        if (write_tail && t == SEQ - 1) __stcg(out + (size_t)SEQ * BH + oidx, hv);

        // grid barrier: absolute target, 1 atomic + 1 volatile poller per block
        if (t < SEQ - 1) {
            __threadfence();
            __syncthreads();
            if (tid == 0) {
                const unsigned target = (unsigned)(t + 1) * GRID_P;
                atomicAdd(&g_count, 1u);
                while (*((volatile unsigned*)&g_count) < target) { }
            }
            __syncthreads();
        }
    }
}

// ===========================================================================
extern "C" void kernel_launch(void* const* d_in, const int* in_sizes, int n_in,
                              void* d_out, int out_size) {
    const float* x   = (const float*)d_in[0];
    const float* h0  = (const float*)d_in[1];
    const float* Wih = (const float*)d_in[2];
    const float* bih = (const float*)d_in[3];
    const float* Whh = (const float*)d_in[4];
    const float* bhh = (const float*)d_in[5];
    float* out = (float*)d_out;

    input_gemm_kernel<<<dim3(D_H / 128, M_IN / 128), 256>>>(x, Wih, bih, bhh, out);

    long long total = (long long)SEQ * BH;
    int write_tail = ((long long)out_size >= total + BH) ? 1 : 0;
    rnn_persistent_kernel<<<GRID_P, 512>>>(h0, Whh, out, write_tail);
}

// round 11
// speedup vs baseline: 2.9773x; 2.9773x over previous
#include <cuda_runtime.h>
#include <cuda_bf16.h>
#include <math.h>
#include <stdint.h>

#define SEQ    512
#define BATCH  64
#define D_IN   1024
#define D_H    1024
#define M_IN   (SEQ * BATCH)      // 32768
#define BH     (BATCH * D_H)      // 65536
#define GRID_P 128                // persistent blocks for recurrence

typedef unsigned long long ull;

// packed f32x2 helpers (FFMA2: only reachable via PTX fma.rn.f32x2)
__device__ __forceinline__ ull pk2(float lo, float hi) {
    ull r;
    asm("mov.b64 %0, {%1, %2};" : "=l"(r) : "r"(__float_as_uint(lo)), "r"(__float_as_uint(hi)));
    return r;
}
__device__ __forceinline__ void upk2(float& lo, float& hi, ull v) {
    uint32_t a, b;
    asm("mov.b64 {%0, %1}, %2;" : "=r"(a), "=r"(b) : "l"(v));
    lo = __uint_as_float(a); hi = __uint_as_float(b);
}
__device__ __forceinline__ ull fma2(ull a, ull b, ull c) {
    ull d;
    asm("fma.rn.f32x2 %0, %1, %2, %3;" : "=l"(d) : "l"(a), "l"(b), "l"(c));
    return d;
}

// ===========================================================================
// Persistent device state: barrier counter. Reset to 0 by the GEMM kernel
// (stream-ordered before the rnn kernel), so every run uses absolute targets.
// ===========================================================================
__device__ unsigned g_count;

// ===========================================================================
// Input projection: out[m][n] = sum_i x[m][i]*Wih[n][i] + bih[n] + bhh[n]
// M=32768, N=1024, K=1024. BM=BN=128, BK=16, 8x8 thread tile, 256 threads.
// (R8-proven body.) Block (0,0) resets the rnn barrier counter.
// ===========================================================================
__global__ __launch_bounds__(256) void input_gemm_kernel(
    const float* __restrict__ x, const float* __restrict__ Wih,
    const float* __restrict__ bih, const float* __restrict__ bhh,
    float* __restrict__ out)
{
    __shared__ __align__(16) float As[16][132];
    __shared__ __align__(16) float Bs[16][132];

    const int tid = threadIdx.x;
    if (blockIdx.x == 0 && blockIdx.y == 0 && tid == 0) g_count = 0u;

    const int m0 = blockIdx.y * 128;
    const int n0 = blockIdx.x * 128;
    const int tx = tid & 15;   // -> n
    const int ty = tid >> 4;   // -> m

    ull acc2[8][4];
    #pragma unroll
    for (int i = 0; i < 8; i++)
        #pragma unroll
        for (int j = 0; j < 4; j++) acc2[i][j] = 0ull;

    for (int k0 = 0; k0 < D_IN; k0 += 16) {
        #pragma unroll
        for (int l = 0; l < 2; l++) {
            int f = tid + l * 256;
            int r = f >> 2, c = (f & 3) * 4;
            float4 v = *(const float4*)(x + (size_t)(m0 + r) * D_IN + k0 + c);
            As[c + 0][r] = v.x; As[c + 1][r] = v.y;
            As[c + 2][r] = v.z; As[c + 3][r] = v.w;
        }
        #pragma unroll
        for (int l = 0; l < 2; l++) {
            int f = tid + l * 256;
            int r = f >> 2, c = (f & 3) * 4;
            float4 v = *(const float4*)(Wih + (size_t)(n0 + r) * D_IN + k0 + c);
            Bs[c + 0][r] = v.x; Bs[c + 1][r] = v.y;
            Bs[c + 2][r] = v.z; Bs[c + 3][r] = v.w;
        }
        __syncthreads();
        #pragma unroll
        for (int k = 0; k < 16; k++) {
            float a[8], b[8];
            *(float4*)&a[0] = *(const float4*)&As[k][ty * 8];
            *(float4*)&a[4] = *(const float4*)&As[k][ty * 8 + 4];
            *(float4*)&b[0] = *(const float4*)&Bs[k][tx * 8];
            *(float4*)&b[4] = *(const float4*)&Bs[k][tx * 8 + 4];
            ull b2[4];
            #pragma unroll
            for (int q = 0; q < 4; q++) b2[q] = pk2(b[2 * q], b[2 * q + 1]);
            #pragma unroll
            for (int i = 0; i < 8; i++) {
                ull a2 = pk2(a[i], a[i]);
                #pragma unroll
                for (int q = 0; q < 4; q++)
                    acc2[i][q] = fma2(a2, b2[q], acc2[i][q]);
            }
        }
        __syncthreads();
    }

    #pragma unroll
    for (int i = 0; i < 8; i++) {
        int m = m0 + ty * 8 + i;
        float accf[8];
        #pragma unroll
        for (int q = 0; q < 4; q++) upk2(accf[2 * q], accf[2 * q + 1], acc2[i][q]);
        #pragma unroll
        for (int j = 0; j < 8; j += 4) {
            int n = n0 + tx * 8 + j;
            float4 o;
            o.x = accf[j + 0] + bih[n + 0] + bhh[n + 0];
            o.y = accf[j + 1] + bih[n + 1] + bhh[n + 1];
            o.z = accf[j + 2] + bih[n + 2] + bhh[n + 2];
            o.w = accf[j + 3] + bih[n + 3] + bhh[n + 3];
            *(float4*)(out + (size_t)m * D_H + n) = o;
        }
    }
}

// ===========================================================================
// Persistent recurrence, coalesced + conflict-free.
// 128 blocks x 512 threads. Block bx owns cols j0 = bx*8.
// Thread (bg = tid>>5, lane): 4 batches (bg*4..+3) x 8 cols; lane's k-set is
// the INTERLEAVED set {4*lane + 128*i + c} so warp h-loads are 32 consecutive
// float4 (4 wavefronts, was 32). W in smem with skew addr_u64(k,jp) =
// k*4 + (k>>2)*2 + jp -> lane bank start 4l+8c mod 32, phase-balanced.
// Reduction: R10-proven 31-shfl halving butterfly (lane l -> output l).
// h state lives in out: step t reads out[t-1] (t=0: h0).
// ===========================================================================
__global__ __launch_bounds__(512, 1) void rnn_persistent_kernel(
    const float* __restrict__ h0, const float* __restrict__ Whh,
    float* __restrict__ out, int write_tail)
{
    __shared__ __align__(16) ull Ws2[4616];   // 1024 k * 4.5 u64 avg = 36928 B

    const int tid = threadIdx.x;
    const int bx  = blockIdx.x;
    const int j0  = bx * 8;

    // One-time Whh slice load into skewed layout:
    // Ws2[k*4 + (k>>2)*2 + jp] = (W[j0+2jp][k], W[j0+2jp+1][k])
    {
        const int k = tid * 2;                     // k, k+1 share a quad
        const int base = k * 4 + (k >> 2) * 2;
        #pragma unroll
        for (int jp = 0; jp < 4; jp++) {
            float2 wa = *(const float2*)(Whh + (size_t)(j0 + 2 * jp) * D_H + k);
            float2 wb = *(const float2*)(Whh + (size_t)(j0 + 2 * jp + 1) * D_H + k);
            Ws2[base + jp]     = pk2(wa.x, wb.x);
            Ws2[base + 4 + jp] = pk2(wa.y, wb.y);
        }
    }
    __syncthreads();

    const int bg   = tid >> 5;        // 0..15 batch group
    const int lane = tid & 31;
    const int b0   = bg * 4;
    const ull* wl  = Ws2 + 18 * lane; // lane base of the skewed layout

    // after reduction, lane l owns output (b0 + (l>>3), j0 + (l&7))
    const int oidx = (b0 + (lane >> 3)) * D_H + j0 + (lane & 7);

    for (int t = 0; t < SEQ; t++) {
        const float* hsrc = (t == 0) ? h0 : out + (size_t)(t - 1) * BH;
        float* op = out + (size_t)t * BH + oidx;

        // prefetch xproj early (off the critical path)
        float xp = __ldcg(op);

        ull acc[4][4];                // [bb][jp]
        #pragma unroll
        for (int bb = 0; bb < 4; bb++)
            #pragma unroll
            for (int jp = 0; jp < 4; jp++) acc[bb][jp] = 0ull;

        #pragma unroll
        for (int i = 0; i < 8; i++) {
            // warp-coalesced: lanes read 32 consecutive float4 of one batch row
            float4 hv[4];
            #pragma unroll
            for (int bb = 0; bb < 4; bb++)
                hv[bb] = __ldcg((const float4*)(hsrc + (size_t)(b0 + bb) * D_H
                                                + i * 128 + lane * 4));
            const ull* wi = wl + 576 * i;
            #pragma unroll
            for (int c = 0; c < 4; c++) {          // k = 4*lane + 128*i + c
                ulonglong2 wA = *(const ulonglong2*)(wi + 4 * c);
                ulonglong2 wB = *(const ulonglong2*)(wi + 4 * c + 2);
                #pragma unroll
                for (int bb = 0; bb < 4; bb++) {
                    float hk = ((const float*)&hv[bb])[c];
                    ull h2 = pk2(hk, hk);
                    acc[bb][0] = fma2(h2, wA.x, acc[bb][0]);
                    acc[bb][1] = fma2(h2, wA.y, acc[bb][1]);
                    acc[bb][2] = fma2(h2, wB.x, acc[bb][2]);
                    acc[bb][3] = fma2(h2, wB.y, acc[bb][3]);
                }
            }
        }

        // unpack to v[a], a = bb*8 + col (col = 2*jp + p)
        float v[32];
        #pragma unroll
        for (int bb = 0; bb < 4; bb++)
            #pragma unroll
            for (int jp = 0; jp < 4; jp++)
                upk2(v[bb * 8 + 2 * jp], v[bb * 8 + 2 * jp + 1], acc[bb][jp]);

        // halving butterfly: lane l ends with the full sum of v[l]
        #pragma unroll
        for (int s = 0; s < 5; s++) {
            const int m = 16 >> s;         // 16,8,4,2,1
            const bool hi = (lane & m) != 0;
            #pragma unroll
            for (int q = 0; q < 16; q++) { // only q < m is live
                if (q < m) {
                    float tsend = hi ? v[q] : v[q + m];
                    float r = __shfl_xor_sync(0xffffffffu, tsend, m);
                    v[q] = (hi ? v[q + m] : v[q]) + r;
                }
            }
        }

        float hv = tanhf(xp + v[0]);
        __stcg(op, hv);
        if (write_tail && t == SEQ - 1) __stcg(out + (size_t)SEQ * BH + oidx, hv);

        // grid barrier: absolute target, 1 atomic + 1 volatile poller per block
        if (t < SEQ - 1) {
            __threadfence();
            __syncthreads();
            if (tid == 0) {
                const unsigned target = (unsigned)(t + 1) * GRID_P;
                atomicAdd(&g_count, 1u);
                while (*((volatile unsigned*)&g_count) < target) { }
            }
            __syncthreads();
        }
    }
}

// ===========================================================================
extern "C" void kernel_launch(void* const* d_in, const int* in_sizes, int n_in,
                              void* d_out, int out_size) {
    const float* x   = (const float*)d_in[0];
    const float* h0  = (const float*)d_in[1];
    const float* Wih = (const float*)d_in[2];
    const float* bih = (const float*)d_in[3];
    const float* Whh = (const float*)d_in[4];
    const float* bhh = (const float*)d_in[5];
    float* out = (float*)d_out;

    input_gemm_kernel<<<dim3(D_H / 128, M_IN / 128), 256>>>(x, Wih, bih, bhh, out);

    long long total = (long long)SEQ * BH;
    int write_tail = ((long long)out_size >= total + BH) ? 1 : 0;
    rnn_persistent_kernel<<<GRID_P, 512>>>(h0, Whh, out, write_tail);
}